// round 1
// baseline (speedup 1.0000x reference)
#include <cuda_runtime.h>
#include <cstdint>
#include <cstddef>

// Problem constants
#define B_  8
#define H_  16
#define L_  4096
#define D_  64
#define M_  8      // log_lk
#define C_  5
#define CTX_ELEMS ((size_t)B_*H_*L_*D_)   // 33554432

// Scratch (device globals; no allocation allowed)
__device__ float g_Ks[B_*H_*M_*D_];    // 65536
__device__ float g_Vs[B_*H_*M_*D_];
__device__ float g_attn[(size_t)H_*L_*M_];  // 524288
__device__ int   g_zero;               // 1 if a keep==0 cluster exists for batch 0
__device__ float g_loss;

// ---------------------------------------------------------------------------
// Kernel A: Ks[b,h,m,d] = sum_l K[b,h,l,d]*W_sk[m,l] + b_sk[m]  (and same for V)
// 128 blocks (one per (b,h)), 256 threads = 4 split-K groups of 64 (thread owns d,
// 8 m-accumulators per array). smem-staged chunks of 64 l.
// ---------------------------------------------------------------------------
__global__ __launch_bounds__(256, 4)
void shrink_kernel(const float* __restrict__ K, const float* __restrict__ V,
                   const float* __restrict__ Wsk, const float* __restrict__ bsk,
                   const float* __restrict__ Wsv, const float* __restrict__ bsv)
{
    __shared__ float sK[64*64];      // 16KB
    __shared__ float sV[64*64];      // 16KB
    __shared__ float4 sWk4[64*2];    // [ll][m as 2xfloat4]
    __shared__ float4 sWv4[64*2];

    const int tid = threadIdx.x;
    const int bh  = blockIdx.x;            // 0..127
    const int g   = tid >> 6;              // split-K group 0..3
    const int d   = tid & 63;
    const int gbase = g * 16;

    const float* Kbh = K + (size_t)bh * L_ * D_;
    const float* Vbh = V + (size_t)bh * L_ * D_;
    float4* sK4 = reinterpret_cast<float4*>(sK);
    float4* sV4 = reinterpret_cast<float4*>(sV);
    float*  sWkF = reinterpret_cast<float*>(sWk4);
    float*  sWvF = reinterpret_cast<float*>(sWv4);

    float ak[8], av[8];
#pragma unroll
    for (int m = 0; m < 8; ++m) { ak[m] = 0.f; av[m] = 0.f; }

    for (int c0 = 0; c0 < L_; c0 += 64) {
        const float4* Kg = reinterpret_cast<const float4*>(Kbh + (size_t)c0 * D_);
        const float4* Vg = reinterpret_cast<const float4*>(Vbh + (size_t)c0 * D_);
#pragma unroll
        for (int i = 0; i < 4; ++i) {
            sK4[i*256 + tid] = Kg[i*256 + tid];
            sV4[i*256 + tid] = Vg[i*256 + tid];
        }
#pragma unroll
        for (int id = tid; id < 512; id += 256) {
            int m  = id >> 6;
            int ll = id & 63;
            sWkF[ll*8 + m] = Wsk[m*L_ + c0 + ll];
            sWvF[ll*8 + m] = Wsv[m*L_ + c0 + ll];
        }
        __syncthreads();
#pragma unroll
        for (int i = 0; i < 16; ++i) {
            int ll = gbase + i;
            float kk = sK[ll*64 + d];
            float vv = sV[ll*64 + d];
            float4 wk0 = sWk4[ll*2], wk1 = sWk4[ll*2 + 1];
            float4 wv0 = sWv4[ll*2], wv1 = sWv4[ll*2 + 1];
            ak[0] = fmaf(kk, wk0.x, ak[0]); ak[1] = fmaf(kk, wk0.y, ak[1]);
            ak[2] = fmaf(kk, wk0.z, ak[2]); ak[3] = fmaf(kk, wk0.w, ak[3]);
            ak[4] = fmaf(kk, wk1.x, ak[4]); ak[5] = fmaf(kk, wk1.y, ak[5]);
            ak[6] = fmaf(kk, wk1.z, ak[6]); ak[7] = fmaf(kk, wk1.w, ak[7]);
            av[0] = fmaf(vv, wv0.x, av[0]); av[1] = fmaf(vv, wv0.y, av[1]);
            av[2] = fmaf(vv, wv0.z, av[2]); av[3] = fmaf(vv, wv0.w, av[3]);
            av[4] = fmaf(vv, wv1.x, av[4]); av[5] = fmaf(vv, wv1.y, av[5]);
            av[6] = fmaf(vv, wv1.z, av[6]); av[7] = fmaf(vv, wv1.w, av[7]);
        }
        __syncthreads();
    }

    // cross-group reduction (reuse sK: 4096 floats; K parts [0,2048), V [2048,4096))
    float* red = sK;
#pragma unroll
    for (int m = 0; m < 8; ++m) {
        red[(g*8 + m)*64 + d]        = ak[m];
        red[2048 + (g*8 + m)*64 + d] = av[m];
    }
    __syncthreads();
    for (int j = tid; j < 512; j += 256) {
        int m  = j >> 6;
        int dd = j & 63;
        float sk_ = 0.f, sv_ = 0.f;
#pragma unroll
        for (int gg = 0; gg < 4; ++gg) {
            sk_ += red[(gg*8 + m)*64 + dd];
            sv_ += red[2048 + (gg*8 + m)*64 + dd];
        }
        size_t o = ((size_t)bh * 8 + m) * 64 + dd;
        g_Ks[o] = sk_ + bsk[m];
        g_Vs[o] = sv_ + bsv[m];
    }
}

// ---------------------------------------------------------------------------
// Kernel B: cluster projections, loss, argmax(cq[0]) -> g_zero, loss -> out tail
// single block, 256 threads
// ---------------------------------------------------------------------------
__global__ __launch_bounds__(256, 1)
void cluster_kernel(const float* __restrict__ Wpc, const float* __restrict__ bpc,
                    const float* __restrict__ Wq,  const float* __restrict__ bq,
                    const float* __restrict__ Wk,  const float* __restrict__ bk,
                    float* __restrict__ out, long long out_size)
{
    const int tid = threadIdx.x;
    __shared__ float zred[B_*C_];   // 40
    if (tid < B_*C_) zred[tid] = 0.f;
    __syncthreads();

    // z-pre: acc[b][c] = sum_i flat[b,i] * Wpc[c,i], flat[b,i] = g_Ks[b*8192+i]
    float acc[B_][C_];
#pragma unroll
    for (int b = 0; b < B_; ++b)
#pragma unroll
        for (int c = 0; c < C_; ++c) acc[b][c] = 0.f;

    for (int i = tid; i < H_*M_*D_; i += 256) {   // 8192
        float w[C_];
#pragma unroll
        for (int c = 0; c < C_; ++c) w[c] = Wpc[c*8192 + i];
#pragma unroll
        for (int b = 0; b < B_; ++b) {
            float f = g_Ks[b*8192 + i];
#pragma unroll
            for (int c = 0; c < C_; ++c) acc[b][c] = fmaf(f, w[c], acc[b][c]);
        }
    }
    // warp reduce then atomic into smem
#pragma unroll
    for (int b = 0; b < B_; ++b)
#pragma unroll
        for (int c = 0; c < C_; ++c) {
            float v = acc[b][c];
#pragma unroll
            for (int off = 16; off; off >>= 1) v += __shfl_xor_sync(0xffffffffu, v, off);
            if ((tid & 31) == 0) atomicAdd(&zred[b*C_ + c], v);
        }
    __syncthreads();

    if (tid == 0) {
        float z[B_][C_], cq[B_][C_], ck[B_][C_];
        for (int b = 0; b < B_; ++b)
            for (int c = 0; c < C_; ++c) {
                float v = zred[b*C_ + c] + bpc[c];
                z[b][c] = v > 0.f ? v : 0.f;
            }
        // cq, ck (softmax of z @ W^T + bias)
        for (int b = 0; b < B_; ++b) {
            float lq[C_], lk_[C_];
            for (int c = 0; c < C_; ++c) {
                float sq = bq[c], sk = bk[c];
                for (int j = 0; j < C_; ++j) {
                    sq = fmaf(z[b][j], Wq[c*C_ + j], sq);
                    sk = fmaf(z[b][j], Wk[c*C_ + j], sk);
                }
                lq[c] = sq; lk_[c] = sk;
            }
            float mq = lq[0], mk = lk_[0];
            for (int c = 1; c < C_; ++c) { mq = fmaxf(mq, lq[c]); mk = fmaxf(mk, lk_[c]); }
            float sq = 0.f, sk = 0.f;
            for (int c = 0; c < C_; ++c) { lq[c] = expf(lq[c]-mq); sq += lq[c];
                                           lk_[c] = expf(lk_[c]-mk); sk += lk_[c]; }
            for (int c = 0; c < C_; ++c) { cq[b][c] = lq[c]/sq; ck[b][c] = lk_[c]/sk; }
        }
        // mu = mean_b cq; sigma = softplus(std(ck, ddof=1))
        float mu[C_], sigma[C_];
        for (int c = 0; c < C_; ++c) {
            float s = 0.f, sc = 0.f;
            for (int b = 0; b < B_; ++b) { s += cq[b][c]; sc += ck[b][c]; }
            mu[c] = s / B_;
            float mck = sc / B_;
            float var = 0.f;
            for (int b = 0; b < B_; ++b) { float dlt = ck[b][c]-mck; var += dlt*dlt; }
            var /= (B_ - 1);
            float sd = sqrtf(var);
            sigma[c] = log1pf(expf(sd));
        }
        const float HL2PI = 0.9189385332046727f; // 0.5*log(2*pi)
        float sumlp = 0.f;
        for (int b = 0; b < B_; ++b)
            for (int c = 0; c < C_; ++c) {
                float t = (ck[b][c] - mu[c]) / sigma[c];
                sumlp += -0.5f*t*t - logf(sigma[c]) - HL2PI;
            }
        float mean_lp = sumlp / (B_*C_);
        // ce = mean_b( -sum_c cq * log_softmax(cq) )
        float ce = 0.f;
        for (int b = 0; b < B_; ++b) {
            float mx = cq[b][0];
            for (int c = 1; c < C_; ++c) mx = fmaxf(mx, cq[b][c]);
            float se = 0.f;
            for (int c = 0; c < C_; ++c) se += expf(cq[b][c]-mx);
            float lse = mx + logf(se);
            float s = 0.f;
            for (int c = 0; c < C_; ++c) s += cq[b][c] * (cq[b][c] - lse);
            ce += -s;
        }
        ce /= B_;
        float loss = -mean_lp + ce;
        g_loss = loss;
        // argmax(cq[0]) (first max, jnp semantics)
        int ind0 = 0; float best = cq[0][0];
        for (int c = 1; c < C_; ++c) if (cq[0][c] > best) { best = cq[0][c]; ind0 = c; }
        g_zero = (ind0 >= 1) ? 1 : 0;
        // loss goes after context in flattened output
        for (long long j = (long long)CTX_ELEMS; j < out_size; ++j) out[j] = loss;
    }
}

// ---------------------------------------------------------------------------
// Kernel C: attn[h,q,k] from Q[0], Ks[0], mask + two-branch max + softmax
// grid 8192 (h*512), 256 threads = 8 warps, warp per q-row
// ---------------------------------------------------------------------------
__global__ __launch_bounds__(256, 8)
void attn_kernel(const float* __restrict__ Q)
{
    __shared__ float sKs[M_*D_];   // 512 floats: Ks[0,h]
    const int tid  = threadIdx.x;
    const int h    = blockIdx.x >> 9;
    const int qblk = blockIdx.x & 511;
    for (int j = tid; j < M_*D_; j += 256) sKs[j] = g_Ks[(size_t)h*M_*D_ + j]; // b=0
    __syncthreads();

    const int warp = tid >> 5, lane = tid & 31;
    const int q = qblk*8 + warp;
    const float* Qrow = Q + ((size_t)h * L_ + q) * D_;   // batch 0
    float qv0 = Qrow[lane], qv1 = Qrow[lane + 32];

    float base[8];
#pragma unroll
    for (int k = 0; k < 8; ++k) {
        float p = qv0 * sKs[k*64 + lane] + qv1 * sKs[k*64 + lane + 32];
#pragma unroll
        for (int off = 16; off; off >>= 1) p += __shfl_xor_sync(0xffffffffu, p, off);
        base[k] = p * 0.125f;   // /sqrt(64)
    }
    // case A: masked softmax of base, *8
    float s[8], mx = -1e30f;
#pragma unroll
    for (int k = 0; k < 8; ++k) { s[k] = (k <= q) ? -1e9f : base[k]; mx = fmaxf(mx, s[k]); }
    float sum = 0.f, e[8];
#pragma unroll
    for (int k = 0; k < 8; ++k) { e[k] = expf(s[k]-mx); sum += e[k]; }
    float f[8];
#pragma unroll
    for (int k = 0; k < 8; ++k) f[k] = 8.f * e[k] / sum;
    // case B (keep==0 cluster exists): base==0 row, closed form
    if (g_zero) {
#pragma unroll
        for (int k = 0; k < 8; ++k) {
            float bv;
            if (q >= 7)      bv = 1.f;
            else if (k > q)  bv = 8.f / (float)(7 - q);
            else             bv = 0.f;
            f[k] = fmaxf(f[k], bv);
        }
    }
    // final softmax
    mx = f[0];
#pragma unroll
    for (int k = 1; k < 8; ++k) mx = fmaxf(mx, f[k]);
    sum = 0.f;
#pragma unroll
    for (int k = 0; k < 8; ++k) { e[k] = expf(f[k]-mx); sum += e[k]; }
    if (lane < 8)
        g_attn[((size_t)h * L_ + q) * M_ + lane] = e[lane] / sum;
}

// ---------------------------------------------------------------------------
// Kernel D: context[b,h,q,d] = sum_k attn[h,q,k] * Vs[b,h,k,d]
// grid 4096 (b*512 + h*32 + qtile), 256 threads, float4 coalesced stores
// ---------------------------------------------------------------------------
__global__ __launch_bounds__(256, 8)
void ctx_kernel(float* __restrict__ out)
{
    const int tid = threadIdx.x;
    const int qt  = blockIdx.x & 31;
    const int h   = (blockIdx.x >> 5) & 15;
    const int b   = blockIdx.x >> 9;

    __shared__ float4 sV4[M_*16];     // Vs[b,h]: 8 k x 64 d
    __shared__ float4 sA4[128*2];     // attn: 128 q x 8 k

    for (int j = tid; j < M_*D_; j += 256)
        reinterpret_cast<float*>(sV4)[j] = g_Vs[(((size_t)b*H_ + h) * M_) * D_ + j];
    for (int j = tid; j < 128*M_; j += 256)
        reinterpret_cast<float*>(sA4)[j] = g_attn[((size_t)h * L_ + qt*128) * M_ + j];
    __syncthreads();

    const int dq = tid & 15;    // float4 column
    const int q0 = tid >> 4;    // 0..15
    float4* out4 = reinterpret_cast<float4*>(out)
                 + (((size_t)b*H_ + h) * L_ + (size_t)qt*128) * 16;
#pragma unroll
    for (int i = 0; i < 8; ++i) {
        int ql = i*16 + q0;
        float4 a0 = sA4[ql*2], a1 = sA4[ql*2 + 1];
        float aw[8] = {a0.x, a0.y, a0.z, a0.w, a1.x, a1.y, a1.z, a1.w};
        float4 acc = make_float4(0.f, 0.f, 0.f, 0.f);
#pragma unroll
        for (int k = 0; k < 8; ++k) {
            float4 v = sV4[k*16 + dq];
            acc.x = fmaf(aw[k], v.x, acc.x);
            acc.y = fmaf(aw[k], v.y, acc.y);
            acc.z = fmaf(aw[k], v.z, acc.z);
            acc.w = fmaf(aw[k], v.w, acc.w);
        }
        out4[(size_t)ql*16 + dq] = acc;
    }
}

// ---------------------------------------------------------------------------
extern "C" void kernel_launch(void* const* d_in, const int* in_sizes, int n_in,
                              void* d_out, int out_size)
{
    const float* Q   = (const float*)d_in[0];
    const float* K   = (const float*)d_in[1];
    const float* V   = (const float*)d_in[2];
    const float* Wsk = (const float*)d_in[3];
    const float* bsk = (const float*)d_in[4];
    const float* Wsv = (const float*)d_in[5];
    const float* bsv = (const float*)d_in[6];
    const float* Wpc = (const float*)d_in[7];
    const float* bpc = (const float*)d_in[8];
    const float* Wq  = (const float*)d_in[9];
    const float* bq  = (const float*)d_in[10];
    const float* Wk  = (const float*)d_in[11];
    const float* bk  = (const float*)d_in[12];
    float* out = (float*)d_out;

    shrink_kernel<<<B_*H_, 256>>>(K, V, Wsk, bsk, Wsv, bsv);
    cluster_kernel<<<1, 256>>>(Wpc, bpc, Wq, bq, Wk, bk, out, (long long)out_size);
    attn_kernel<<<H_*512, 256>>>(Q);
    ctx_kernel<<<B_*H_*32, 256>>>(out);
}

// round 2
// speedup vs baseline: 1.6840x; 1.6840x over previous
#include <cuda_runtime.h>
#include <cstdint>
#include <cstddef>

// Problem constants
#define B_  8
#define H_  16
#define L_  4096
#define D_  64
#define M_  8      // log_lk
#define C_  5
#define CTX_ELEMS ((size_t)B_*H_*L_*D_)   // 33554432

typedef unsigned long long u64;

// Scratch (device globals; no allocation allowed)
__device__ float g_partK[4*128*512];   // [ls][bh][m][d] partials
__device__ float g_partV[4*128*512];
__device__ float g_Ks[B_*H_*M_*D_];    // 65536
__device__ float g_Vs[B_*H_*M_*D_];
__device__ float g_attn[(size_t)H_*L_*M_];  // 524288
__device__ int   g_zero;
__device__ float g_loss;

#define FFMA2(acc, a, b) \
    asm("fma.rn.f32x2 %0, %1, %2, %0;" : "+l"(acc) : "l"(a), "l"(b))

// ---------------------------------------------------------------------------
// Kernel A: partial Ks/Vs over an L-slab of 1024.
// grid (128 bh, 4 ls), 256 threads = (lsub 16) x (dq 16). Direct LDG.128 of
// K/V (no staging), W staged in smem as duplicated float2 pairs for FFMA2.
// ---------------------------------------------------------------------------
__global__ __launch_bounds__(256, 2)
void shrink_kernel(const float* __restrict__ K, const float* __restrict__ V,
                   const float* __restrict__ Wsk, const float* __restrict__ Wsv)
{
    __shared__ char sbuf[32768];              // W pairs (2x16KB) then reduction
    float2* sWk = reinterpret_cast<float2*>(sbuf);           // [256][8]
    float2* sWv = reinterpret_cast<float2*>(sbuf + 16384);   // [256][8]

    const int tid  = threadIdx.x;
    const int bh   = blockIdx.x;
    const int ls   = blockIdx.y;
    const int dq   = tid & 15;
    const int lsub = tid >> 4;
    const int l0   = ls * 1024;

    u64 akp[8][2], avp[8][2];
#pragma unroll
    for (int m = 0; m < 8; ++m) { akp[m][0]=0ull; akp[m][1]=0ull; avp[m][0]=0ull; avp[m][1]=0ull; }

    for (int outer = 0; outer < 4; ++outer) {
        const int lb = l0 + outer * 256;
        // stage W chunk duplicated: sW[ll][m] = {w,w}
        for (int j = tid; j < 2048; j += 256) {
            int m = j >> 8, ll = j & 255;
            float wk = Wsk[m*L_ + lb + ll];
            float wv = Wsv[m*L_ + lb + ll];
            sWk[ll*8 + m] = make_float2(wk, wk);
            sWv[ll*8 + m] = make_float2(wv, wv);
        }
        __syncthreads();

        const ulonglong2* K2 = reinterpret_cast<const ulonglong2*>(K + ((size_t)bh*L_ + lb)*D_);
        const ulonglong2* V2 = reinterpret_cast<const ulonglong2*>(V + ((size_t)bh*L_ + lb)*D_);
#pragma unroll 4
        for (int j = 0; j < 16; ++j) {
            int ll = (j << 4) + lsub;
            ulonglong2 kk = K2[ll*16 + dq];
            ulonglong2 vv = V2[ll*16 + dq];
#pragma unroll
            for (int m = 0; m < 8; ++m) {
                u64 wk = *reinterpret_cast<const u64*>(&sWk[ll*8 + m]);
                u64 wv = *reinterpret_cast<const u64*>(&sWv[ll*8 + m]);
                FFMA2(akp[m][0], kk.x, wk);
                FFMA2(akp[m][1], kk.y, wk);
                FFMA2(avp[m][0], vv.x, wv);
                FFMA2(avp[m][1], vv.y, wv);
            }
        }
        __syncthreads();
    }

    // cross-lsub reduction, K then V, reusing sbuf (32KB as float4[2048])
    float4* red = reinterpret_cast<float4*>(sbuf);
    float4* gK4 = reinterpret_cast<float4*>(g_partK);
    float4* gV4 = reinterpret_cast<float4*>(g_partV);

#pragma unroll
    for (int m = 0; m < 8; ++m) {
        float2 f0 = *reinterpret_cast<float2*>(&akp[m][0]);
        float2 f1 = *reinterpret_cast<float2*>(&akp[m][1]);
        red[lsub*128 + m*16 + dq] = make_float4(f0.x, f0.y, f1.x, f1.y);
    }
    __syncthreads();
    if (tid < 128) {
        float4 s = make_float4(0.f,0.f,0.f,0.f);
#pragma unroll
        for (int g = 0; g < 16; ++g) {
            float4 v = red[g*128 + tid];
            s.x += v.x; s.y += v.y; s.z += v.z; s.w += v.w;
        }
        gK4[(size_t)(ls*128 + bh)*128 + tid] = s;
    }
    __syncthreads();
#pragma unroll
    for (int m = 0; m < 8; ++m) {
        float2 f0 = *reinterpret_cast<float2*>(&avp[m][0]);
        float2 f1 = *reinterpret_cast<float2*>(&avp[m][1]);
        red[lsub*128 + m*16 + dq] = make_float4(f0.x, f0.y, f1.x, f1.y);
    }
    __syncthreads();
    if (tid < 128) {
        float4 s = make_float4(0.f,0.f,0.f,0.f);
#pragma unroll
        for (int g = 0; g < 16; ++g) {
            float4 v = red[g*128 + tid];
            s.x += v.x; s.y += v.y; s.z += v.z; s.w += v.w;
        }
        gV4[(size_t)(ls*128 + bh)*128 + tid] = s;
    }
}

// ---------------------------------------------------------------------------
// Reduce partials -> g_Ks/g_Vs (+bias). 64 blocks x 256 threads = 16384 float4.
// ---------------------------------------------------------------------------
__global__ __launch_bounds__(256, 8)
void reduce_kernel(const float* __restrict__ bsk, const float* __restrict__ bsv)
{
    const int i = blockIdx.x * 256 + threadIdx.x;    // float4 index, 0..16383
    const int m = (i >> 4) & 7;
    const float4* gK4 = reinterpret_cast<const float4*>(g_partK);
    const float4* gV4 = reinterpret_cast<const float4*>(g_partV);
    float4 sk = make_float4(0.f,0.f,0.f,0.f), sv = make_float4(0.f,0.f,0.f,0.f);
#pragma unroll
    for (int ls = 0; ls < 4; ++ls) {
        float4 a = gK4[ls*16384 + i];
        float4 b = gV4[ls*16384 + i];
        sk.x += a.x; sk.y += a.y; sk.z += a.z; sk.w += a.w;
        sv.x += b.x; sv.y += b.y; sv.z += b.z; sv.w += b.w;
    }
    float bk_ = bsk[m], bv_ = bsv[m];
    sk.x += bk_; sk.y += bk_; sk.z += bk_; sk.w += bk_;
    sv.x += bv_; sv.y += bv_; sv.z += bv_; sv.w += bv_;
    reinterpret_cast<float4*>(g_Ks)[i] = sk;
    reinterpret_cast<float4*>(g_Vs)[i] = sv;
}

// ---------------------------------------------------------------------------
// Kernel B: cluster projections, loss, argmax(cq[0]) -> g_zero, loss -> out tail
// ---------------------------------------------------------------------------
__global__ __launch_bounds__(256, 1)
void cluster_kernel(const float* __restrict__ Wpc, const float* __restrict__ bpc,
                    const float* __restrict__ Wq,  const float* __restrict__ bq,
                    const float* __restrict__ Wk,  const float* __restrict__ bk,
                    float* __restrict__ out, long long out_size)
{
    const int tid = threadIdx.x;
    __shared__ float zred[B_*C_];
    if (tid < B_*C_) zred[tid] = 0.f;
    __syncthreads();

    float acc[B_][C_];
#pragma unroll
    for (int b = 0; b < B_; ++b)
#pragma unroll
        for (int c = 0; c < C_; ++c) acc[b][c] = 0.f;

    for (int i = tid; i < H_*M_*D_; i += 256) {
        float w[C_];
#pragma unroll
        for (int c = 0; c < C_; ++c) w[c] = Wpc[c*8192 + i];
#pragma unroll
        for (int b = 0; b < B_; ++b) {
            float f = g_Ks[b*8192 + i];
#pragma unroll
            for (int c = 0; c < C_; ++c) acc[b][c] = fmaf(f, w[c], acc[b][c]);
        }
    }
#pragma unroll
    for (int b = 0; b < B_; ++b)
#pragma unroll
        for (int c = 0; c < C_; ++c) {
            float v = acc[b][c];
#pragma unroll
            for (int off = 16; off; off >>= 1) v += __shfl_xor_sync(0xffffffffu, v, off);
            if ((tid & 31) == 0) atomicAdd(&zred[b*C_ + c], v);
        }
    __syncthreads();

    if (tid == 0) {
        float z[B_][C_], cq[B_][C_], ck[B_][C_];
        for (int b = 0; b < B_; ++b)
            for (int c = 0; c < C_; ++c) {
                float v = zred[b*C_ + c] + bpc[c];
                z[b][c] = v > 0.f ? v : 0.f;
            }
        for (int b = 0; b < B_; ++b) {
            float lq[C_], lk_[C_];
            for (int c = 0; c < C_; ++c) {
                float sq = bq[c], sk = bk[c];
                for (int j = 0; j < C_; ++j) {
                    sq = fmaf(z[b][j], Wq[c*C_ + j], sq);
                    sk = fmaf(z[b][j], Wk[c*C_ + j], sk);
                }
                lq[c] = sq; lk_[c] = sk;
            }
            float mq = lq[0], mk = lk_[0];
            for (int c = 1; c < C_; ++c) { mq = fmaxf(mq, lq[c]); mk = fmaxf(mk, lk_[c]); }
            float sq = 0.f, sk = 0.f;
            for (int c = 0; c < C_; ++c) { lq[c] = expf(lq[c]-mq); sq += lq[c];
                                           lk_[c] = expf(lk_[c]-mk); sk += lk_[c]; }
            for (int c = 0; c < C_; ++c) { cq[b][c] = lq[c]/sq; ck[b][c] = lk_[c]/sk; }
        }
        float mu[C_], sigma[C_];
        for (int c = 0; c < C_; ++c) {
            float s = 0.f, sc = 0.f;
            for (int b = 0; b < B_; ++b) { s += cq[b][c]; sc += ck[b][c]; }
            mu[c] = s / B_;
            float mck = sc / B_;
            float var = 0.f;
            for (int b = 0; b < B_; ++b) { float dlt = ck[b][c]-mck; var += dlt*dlt; }
            var /= (B_ - 1);
            sigma[c] = log1pf(expf(sqrtf(var)));
        }
        const float HL2PI = 0.9189385332046727f;
        float sumlp = 0.f;
        for (int b = 0; b < B_; ++b)
            for (int c = 0; c < C_; ++c) {
                float t = (ck[b][c] - mu[c]) / sigma[c];
                sumlp += -0.5f*t*t - logf(sigma[c]) - HL2PI;
            }
        float mean_lp = sumlp / (B_*C_);
        float ce = 0.f;
        for (int b = 0; b < B_; ++b) {
            float mx = cq[b][0];
            for (int c = 1; c < C_; ++c) mx = fmaxf(mx, cq[b][c]);
            float se = 0.f;
            for (int c = 0; c < C_; ++c) se += expf(cq[b][c]-mx);
            float lse = mx + logf(se);
            float s = 0.f;
            for (int c = 0; c < C_; ++c) s += cq[b][c] * (cq[b][c] - lse);
            ce += -s;
        }
        ce /= B_;
        float loss = -mean_lp + ce;
        g_loss = loss;
        int ind0 = 0; float best = cq[0][0];
        for (int c = 1; c < C_; ++c) if (cq[0][c] > best) { best = cq[0][c]; ind0 = c; }
        g_zero = (ind0 >= 1) ? 1 : 0;
        for (long long j = (long long)CTX_ELEMS; j < out_size; ++j) out[j] = loss;
    }
}

// ---------------------------------------------------------------------------
// Kernel C: attn[h,q,k]  (warp per q)
// ---------------------------------------------------------------------------
__global__ __launch_bounds__(256, 8)
void attn_kernel(const float* __restrict__ Q)
{
    __shared__ float sKs[M_*D_];
    const int tid  = threadIdx.x;
    const int h    = blockIdx.x >> 9;
    const int qblk = blockIdx.x & 511;
    for (int j = tid; j < M_*D_; j += 256) sKs[j] = g_Ks[(size_t)h*M_*D_ + j];
    __syncthreads();

    const int warp = tid >> 5, lane = tid & 31;
    const int q = qblk*8 + warp;
    const float* Qrow = Q + ((size_t)h * L_ + q) * D_;
    float qv0 = Qrow[lane], qv1 = Qrow[lane + 32];

    float base[8];
#pragma unroll
    for (int k = 0; k < 8; ++k) {
        float p = qv0 * sKs[k*64 + lane] + qv1 * sKs[k*64 + lane + 32];
#pragma unroll
        for (int off = 16; off; off >>= 1) p += __shfl_xor_sync(0xffffffffu, p, off);
        base[k] = p * 0.125f;
    }
    float s[8], mx = -1e30f;
#pragma unroll
    for (int k = 0; k < 8; ++k) { s[k] = (k <= q) ? -1e9f : base[k]; mx = fmaxf(mx, s[k]); }
    float sum = 0.f, e[8];
#pragma unroll
    for (int k = 0; k < 8; ++k) { e[k] = expf(s[k]-mx); sum += e[k]; }
    float f[8];
#pragma unroll
    for (int k = 0; k < 8; ++k) f[k] = 8.f * e[k] / sum;
    if (g_zero) {
#pragma unroll
        for (int k = 0; k < 8; ++k) {
            float bv;
            if (q >= 7)      bv = 1.f;
            else if (k > q)  bv = 8.f / (float)(7 - q);
            else             bv = 0.f;
            f[k] = fmaxf(f[k], bv);
        }
    }
    mx = f[0];
#pragma unroll
    for (int k = 1; k < 8; ++k) mx = fmaxf(mx, f[k]);
    sum = 0.f;
#pragma unroll
    for (int k = 0; k < 8; ++k) { e[k] = expf(f[k]-mx); sum += e[k]; }
    if (lane < 8)
        g_attn[((size_t)h * L_ + q) * M_ + lane] = e[lane] / sum;
}

// ---------------------------------------------------------------------------
// Kernel D: context via smem tiles + TMA bulk stores (bypass L1/STG path).
// grid 512 = (b, h, qq): each block owns a 1024q x 64d = 256KB contiguous slab,
// written as 16 double-buffered 16KB cp.async.bulk stores.
// ---------------------------------------------------------------------------
__global__ __launch_bounds__(256, 2)
void ctx_kernel(float* __restrict__ out)
{
    __shared__ float4 sV4[M_*16];          // 2KB  Vs[b,h]
    __shared__ float4 sA4[64*2];           // 2KB  attn subtile (64 q x 8 k)
    __shared__ float  sOut[2][4096];       // 32KB double-buffered output tiles

    const int tid = threadIdx.x;
    const int qq  = blockIdx.x & 3;
    const int h   = (blockIdx.x >> 2) & 15;
    const int b   = blockIdx.x >> 6;

    if (tid < 128)
        sV4[tid] = reinterpret_cast<const float4*>(g_Vs)[(size_t)(b*H_ + h)*128 + tid];

    const int dq = tid & 15;
    const int q0 = tid >> 4;
    const size_t outBase = (((size_t)b*H_ + h) * L_ + (size_t)qq*1024) * D_;
    const float4* gA4 = reinterpret_cast<const float4*>(g_attn) +
                        ((size_t)h * L_ + (size_t)qq*1024) * 2;   // 2 float4 per q

    for (int s = 0; s < 16; ++s) {
        const int p = s & 1;
        if (tid == 0 && s >= 2)
            asm volatile("cp.async.bulk.wait_group 1;" ::: "memory");
        __syncthreads();   // buffer p free; prev sA reads done
        if (tid < 128)
            sA4[tid] = gA4[(size_t)s*128 + tid];
        __syncthreads();

        float4* o4 = reinterpret_cast<float4*>(sOut[p]);
#pragma unroll
        for (int i = 0; i < 4; ++i) {
            int ql = i*16 + q0;
            float4 a0 = sA4[ql*2], a1 = sA4[ql*2 + 1];
            float aw[8] = {a0.x, a0.y, a0.z, a0.w, a1.x, a1.y, a1.z, a1.w};
            float4 acc = make_float4(0.f, 0.f, 0.f, 0.f);
#pragma unroll
            for (int k = 0; k < 8; ++k) {
                float4 v = sV4[k*16 + dq];
                acc.x = fmaf(aw[k], v.x, acc.x);
                acc.y = fmaf(aw[k], v.y, acc.y);
                acc.z = fmaf(aw[k], v.z, acc.z);
                acc.w = fmaf(aw[k], v.w, acc.w);
            }
            o4[ql*16 + dq] = acc;
        }
        __syncthreads();
        if (tid == 0) {
            asm volatile("fence.proxy.async.shared::cta;" ::: "memory");
            unsigned int saddr = (unsigned int)__cvta_generic_to_shared(&sOut[p][0]);
            const float* gdst = out + outBase + (size_t)s * 4096;
            asm volatile("cp.async.bulk.global.shared::cta.bulk_group [%0], [%1], %2;"
                         :: "l"(gdst), "r"(saddr), "r"(16384) : "memory");
            asm volatile("cp.async.bulk.commit_group;" ::: "memory");
        }
    }
    if (tid == 0)
        asm volatile("cp.async.bulk.wait_group 0;" ::: "memory");
}

// ---------------------------------------------------------------------------
extern "C" void kernel_launch(void* const* d_in, const int* in_sizes, int n_in,
                              void* d_out, int out_size)
{
    const float* Q   = (const float*)d_in[0];
    const float* K   = (const float*)d_in[1];
    const float* V   = (const float*)d_in[2];
    const float* Wsk = (const float*)d_in[3];
    const float* bsk = (const float*)d_in[4];
    const float* Wsv = (const float*)d_in[5];
    const float* bsv = (const float*)d_in[6];
    const float* Wpc = (const float*)d_in[7];
    const float* bpc = (const float*)d_in[8];
    const float* Wq  = (const float*)d_in[9];
    const float* bq  = (const float*)d_in[10];
    const float* Wk  = (const float*)d_in[11];
    const float* bk  = (const float*)d_in[12];
    float* out = (float*)d_out;

    shrink_kernel<<<dim3(128, 4), 256>>>(K, V, Wsk, Wsv);
    reduce_kernel<<<64, 256>>>(bsk, bsv);
    cluster_kernel<<<1, 256>>>(Wpc, bpc, Wq, bq, Wk, bk, out, (long long)out_size);
    attn_kernel<<<H_*512, 256>>>(Q);
    ctx_kernel<<<512, 256>>>(out);
}

// round 3
// speedup vs baseline: 2.1303x; 1.2651x over previous
#include <cuda_runtime.h>
#include <cstdint>
#include <cstddef>

// Problem constants
#define B_  8
#define H_  16
#define L_  4096
#define D_  64
#define M_  8      // log_lk
#define C_  5
#define CTX_ELEMS ((size_t)B_*H_*L_*D_)   // 33554432

typedef unsigned long long u64;

// Scratch (device globals; no allocation allowed)
__device__ float g_partK[4*128*512];   // [ls][bh][m][d] partials
__device__ float g_partV[4*128*512];
__device__ float g_Ks[B_*H_*M_*D_];    // 65536
__device__ float g_Vs[B_*H_*M_*D_];
__device__ float g_attn[(size_t)H_*L_*M_];  // 524288
__device__ int   g_zero;
__device__ float g_loss;

#define FFMA2(acc, a, b) \
    asm("fma.rn.f32x2 %0, %1, %2, %0;" : "+l"(acc) : "l"(a), "l"(b))

// ---------------------------------------------------------------------------
// Kernel A: partial Ks/Vs over an L-slab of 1024.
// grid (128 bh, 4 ls), 256 threads = (lsub 16) x (dq 16). Direct LDG.128 of
// K/V (no staging), W staged in smem as duplicated float2 pairs for FFMA2.
// ---------------------------------------------------------------------------
__global__ __launch_bounds__(256, 2)
void shrink_kernel(const float* __restrict__ K, const float* __restrict__ V,
                   const float* __restrict__ Wsk, const float* __restrict__ Wsv)
{
    __shared__ char sbuf[32768];              // W pairs (2x16KB) then reduction
    float2* sWk = reinterpret_cast<float2*>(sbuf);           // [256][8]
    float2* sWv = reinterpret_cast<float2*>(sbuf + 16384);   // [256][8]

    const int tid  = threadIdx.x;
    const int bh   = blockIdx.x;
    const int ls   = blockIdx.y;
    const int dq   = tid & 15;
    const int lsub = tid >> 4;
    const int l0   = ls * 1024;

    u64 akp[8][2], avp[8][2];
#pragma unroll
    for (int m = 0; m < 8; ++m) { akp[m][0]=0ull; akp[m][1]=0ull; avp[m][0]=0ull; avp[m][1]=0ull; }

    for (int outer = 0; outer < 4; ++outer) {
        const int lb = l0 + outer * 256;
        for (int j = tid; j < 2048; j += 256) {
            int m = j >> 8, ll = j & 255;
            float wk = Wsk[m*L_ + lb + ll];
            float wv = Wsv[m*L_ + lb + ll];
            sWk[ll*8 + m] = make_float2(wk, wk);
            sWv[ll*8 + m] = make_float2(wv, wv);
        }
        __syncthreads();

        const ulonglong2* K2 = reinterpret_cast<const ulonglong2*>(K + ((size_t)bh*L_ + lb)*D_);
        const ulonglong2* V2 = reinterpret_cast<const ulonglong2*>(V + ((size_t)bh*L_ + lb)*D_);
#pragma unroll 4
        for (int j = 0; j < 16; ++j) {
            int ll = (j << 4) + lsub;
            ulonglong2 kk = K2[ll*16 + dq];
            ulonglong2 vv = V2[ll*16 + dq];
#pragma unroll
            for (int m = 0; m < 8; ++m) {
                u64 wk = *reinterpret_cast<const u64*>(&sWk[ll*8 + m]);
                u64 wv = *reinterpret_cast<const u64*>(&sWv[ll*8 + m]);
                FFMA2(akp[m][0], kk.x, wk);
                FFMA2(akp[m][1], kk.y, wk);
                FFMA2(avp[m][0], vv.x, wv);
                FFMA2(avp[m][1], vv.y, wv);
            }
        }
        __syncthreads();
    }

    // cross-lsub reduction, K then V, reusing sbuf (32KB as float4[2048])
    float4* red = reinterpret_cast<float4*>(sbuf);
    float4* gK4 = reinterpret_cast<float4*>(g_partK);
    float4* gV4 = reinterpret_cast<float4*>(g_partV);

#pragma unroll
    for (int m = 0; m < 8; ++m) {
        float2 f0 = *reinterpret_cast<float2*>(&akp[m][0]);
        float2 f1 = *reinterpret_cast<float2*>(&akp[m][1]);
        red[lsub*128 + m*16 + dq] = make_float4(f0.x, f0.y, f1.x, f1.y);
    }
    __syncthreads();
    if (tid < 128) {
        float4 s = make_float4(0.f,0.f,0.f,0.f);
#pragma unroll
        for (int g = 0; g < 16; ++g) {
            float4 v = red[g*128 + tid];
            s.x += v.x; s.y += v.y; s.z += v.z; s.w += v.w;
        }
        gK4[(size_t)(ls*128 + bh)*128 + tid] = s;
    }
    __syncthreads();
#pragma unroll
    for (int m = 0; m < 8; ++m) {
        float2 f0 = *reinterpret_cast<float2*>(&avp[m][0]);
        float2 f1 = *reinterpret_cast<float2*>(&avp[m][1]);
        red[lsub*128 + m*16 + dq] = make_float4(f0.x, f0.y, f1.x, f1.y);
    }
    __syncthreads();
    if (tid < 128) {
        float4 s = make_float4(0.f,0.f,0.f,0.f);
#pragma unroll
        for (int g = 0; g < 16; ++g) {
            float4 v = red[g*128 + tid];
            s.x += v.x; s.y += v.y; s.z += v.z; s.w += v.w;
        }
        gV4[(size_t)(ls*128 + bh)*128 + tid] = s;
    }
}

// ---------------------------------------------------------------------------
// Reduce partials -> g_Ks/g_Vs (+bias). 64 blocks x 256 threads = 16384 float4.
// ---------------------------------------------------------------------------
__global__ __launch_bounds__(256, 8)
void reduce_kernel(const float* __restrict__ bsk, const float* __restrict__ bsv)
{
    const int i = blockIdx.x * 256 + threadIdx.x;    // float4 index, 0..16383
    const int m = (i >> 4) & 7;
    const float4* gK4 = reinterpret_cast<const float4*>(g_partK);
    const float4* gV4 = reinterpret_cast<const float4*>(g_partV);
    float4 sk = make_float4(0.f,0.f,0.f,0.f), sv = make_float4(0.f,0.f,0.f,0.f);
#pragma unroll
    for (int ls = 0; ls < 4; ++ls) {
        float4 a = gK4[ls*16384 + i];
        float4 b = gV4[ls*16384 + i];
        sk.x += a.x; sk.y += a.y; sk.z += a.z; sk.w += a.w;
        sv.x += b.x; sv.y += b.y; sv.z += b.z; sv.w += b.w;
    }
    float bk_ = bsk[m], bv_ = bsv[m];
    sk.x += bk_; sk.y += bk_; sk.z += bk_; sk.w += bk_;
    sv.x += bv_; sv.y += bv_; sv.z += bv_; sv.w += bv_;
    reinterpret_cast<float4*>(g_Ks)[i] = sk;
    reinterpret_cast<float4*>(g_Vs)[i] = sv;
}

// ---------------------------------------------------------------------------
// Kernel B: cluster projections, loss, argmax(cq[0]) -> g_zero, loss -> out
// float4-vectorized accumulation.
// ---------------------------------------------------------------------------
__global__ __launch_bounds__(256, 1)
void cluster_kernel(const float* __restrict__ Wpc, const float* __restrict__ bpc,
                    const float* __restrict__ Wq,  const float* __restrict__ bq,
                    const float* __restrict__ Wk,  const float* __restrict__ bk,
                    float* __restrict__ out, long long out_size)
{
    const int tid = threadIdx.x;
    __shared__ float zred[B_*C_];
    if (tid < B_*C_) zred[tid] = 0.f;
    __syncthreads();

    float acc[B_][C_];
#pragma unroll
    for (int b = 0; b < B_; ++b)
#pragma unroll
        for (int c = 0; c < C_; ++c) acc[b][c] = 0.f;

    const float4* W4 = reinterpret_cast<const float4*>(Wpc);
    const float4* F4 = reinterpret_cast<const float4*>(g_Ks);
    for (int i4 = tid; i4 < 2048; i4 += 256) {
        float4 w[C_];
#pragma unroll
        for (int c = 0; c < C_; ++c) w[c] = W4[c*2048 + i4];
#pragma unroll
        for (int b = 0; b < B_; ++b) {
            float4 f = F4[b*2048 + i4];
#pragma unroll
            for (int c = 0; c < C_; ++c) {
                acc[b][c] = fmaf(f.x, w[c].x, acc[b][c]);
                acc[b][c] = fmaf(f.y, w[c].y, acc[b][c]);
                acc[b][c] = fmaf(f.z, w[c].z, acc[b][c]);
                acc[b][c] = fmaf(f.w, w[c].w, acc[b][c]);
            }
        }
    }
#pragma unroll
    for (int b = 0; b < B_; ++b)
#pragma unroll
        for (int c = 0; c < C_; ++c) {
            float v = acc[b][c];
#pragma unroll
            for (int off = 16; off; off >>= 1) v += __shfl_xor_sync(0xffffffffu, v, off);
            if ((tid & 31) == 0) atomicAdd(&zred[b*C_ + c], v);
        }
    __syncthreads();

    if (tid == 0) {
        float z[B_][C_], cq[B_][C_], ck[B_][C_];
        for (int b = 0; b < B_; ++b)
            for (int c = 0; c < C_; ++c) {
                float v = zred[b*C_ + c] + bpc[c];
                z[b][c] = v > 0.f ? v : 0.f;
            }
        for (int b = 0; b < B_; ++b) {
            float lq[C_], lk_[C_];
            for (int c = 0; c < C_; ++c) {
                float sq = bq[c], sk = bk[c];
                for (int j = 0; j < C_; ++j) {
                    sq = fmaf(z[b][j], Wq[c*C_ + j], sq);
                    sk = fmaf(z[b][j], Wk[c*C_ + j], sk);
                }
                lq[c] = sq; lk_[c] = sk;
            }
            float mq = lq[0], mk = lk_[0];
            for (int c = 1; c < C_; ++c) { mq = fmaxf(mq, lq[c]); mk = fmaxf(mk, lk_[c]); }
            float sq = 0.f, sk = 0.f;
            for (int c = 0; c < C_; ++c) { lq[c] = expf(lq[c]-mq); sq += lq[c];
                                           lk_[c] = expf(lk_[c]-mk); sk += lk_[c]; }
            for (int c = 0; c < C_; ++c) { cq[b][c] = lq[c]/sq; ck[b][c] = lk_[c]/sk; }
        }
        float mu[C_], sigma[C_];
        for (int c = 0; c < C_; ++c) {
            float s = 0.f, sc = 0.f;
            for (int b = 0; b < B_; ++b) { s += cq[b][c]; sc += ck[b][c]; }
            mu[c] = s / B_;
            float mck = sc / B_;
            float var = 0.f;
            for (int b = 0; b < B_; ++b) { float dlt = ck[b][c]-mck; var += dlt*dlt; }
            var /= (B_ - 1);
            sigma[c] = log1pf(expf(sqrtf(var)));
        }
        const float HL2PI = 0.9189385332046727f;
        float sumlp = 0.f;
        for (int b = 0; b < B_; ++b)
            for (int c = 0; c < C_; ++c) {
                float t = (ck[b][c] - mu[c]) / sigma[c];
                sumlp += -0.5f*t*t - logf(sigma[c]) - HL2PI;
            }
        float mean_lp = sumlp / (B_*C_);
        float ce = 0.f;
        for (int b = 0; b < B_; ++b) {
            float mx = cq[b][0];
            for (int c = 1; c < C_; ++c) mx = fmaxf(mx, cq[b][c]);
            float se = 0.f;
            for (int c = 0; c < C_; ++c) se += expf(cq[b][c]-mx);
            float lse = mx + logf(se);
            float s = 0.f;
            for (int c = 0; c < C_; ++c) s += cq[b][c] * (cq[b][c] - lse);
            ce += -s;
        }
        ce /= B_;
        float loss = -mean_lp + ce;
        g_loss = loss;
        int ind0 = 0; float best = cq[0][0];
        for (int c = 1; c < C_; ++c) if (cq[0][c] > best) { best = cq[0][c]; ind0 = c; }
        g_zero = (ind0 >= 1) ? 1 : 0;
        for (long long j = (long long)CTX_ELEMS; j < out_size; ++j) out[j] = loss;
    }
}

// ---------------------------------------------------------------------------
// Kernel C: attn[h,q,k] — THREAD per q. No shuffles; Ks broadcast from smem;
// packed f32x2 FMA; scalar softmax. grid = h*32 blocks x 128 threads.
// ---------------------------------------------------------------------------
__global__ __launch_bounds__(128, 8)
void attn_kernel(const float* __restrict__ Q)
{
    __shared__ float4 sKs4[M_*16];   // 2KB, Ks[0,h] as float4[k][d4]
    const int tid = threadIdx.x;
    const int h   = blockIdx.x >> 5;
    const int qt  = blockIdx.x & 31;
    if (tid < 128)
        sKs4[tid] = reinterpret_cast<const float4*>(g_Ks)[(size_t)h*128 + tid];
    __syncthreads();

    const int q = qt*128 + tid;
    const float4* Qrow = reinterpret_cast<const float4*>(Q + ((size_t)h*L_ + q)*D_);

    u64 acc2[8][2];
#pragma unroll
    for (int k = 0; k < 8; ++k) { acc2[k][0] = 0ull; acc2[k][1] = 0ull; }

#pragma unroll
    for (int d4 = 0; d4 < 16; ++d4) {
        float4 qv = Qrow[d4];
        ulonglong2 qu = *reinterpret_cast<const ulonglong2*>(&qv);
#pragma unroll
        for (int k = 0; k < 8; ++k) {
            float4 kv = sKs4[k*16 + d4];
            ulonglong2 ku = *reinterpret_cast<const ulonglong2*>(&kv);
            FFMA2(acc2[k][0], qu.x, ku.x);
            FFMA2(acc2[k][1], qu.y, ku.y);
        }
    }

    float base[8];
#pragma unroll
    for (int k = 0; k < 8; ++k) {
        float2 a = *reinterpret_cast<float2*>(&acc2[k][0]);
        float2 b = *reinterpret_cast<float2*>(&acc2[k][1]);
        base[k] = (a.x + a.y + b.x + b.y) * 0.125f;
    }

    // case A: masked softmax of base, *8
    float s[8], mx = -1e30f;
#pragma unroll
    for (int k = 0; k < 8; ++k) { s[k] = (k <= q) ? -1e9f : base[k]; mx = fmaxf(mx, s[k]); }
    float sum = 0.f, e[8];
#pragma unroll
    for (int k = 0; k < 8; ++k) { e[k] = expf(s[k]-mx); sum += e[k]; }
    float rs = 8.f / sum;
    float f[8];
#pragma unroll
    for (int k = 0; k < 8; ++k) f[k] = e[k] * rs;
    // case B (keep==0 cluster exists): base==0 row, closed form
    if (g_zero) {
#pragma unroll
        for (int k = 0; k < 8; ++k) {
            float bv;
            if (q >= 7)      bv = 1.f;
            else if (k > q)  bv = 8.f / (float)(7 - q);
            else             bv = 0.f;
            f[k] = fmaxf(f[k], bv);
        }
    }
    // final softmax over k
    mx = f[0];
#pragma unroll
    for (int k = 1; k < 8; ++k) mx = fmaxf(mx, f[k]);
    sum = 0.f;
#pragma unroll
    for (int k = 0; k < 8; ++k) { e[k] = expf(f[k]-mx); sum += e[k]; }
    float inv = 1.f / sum;
    float4 o0 = make_float4(e[0]*inv, e[1]*inv, e[2]*inv, e[3]*inv);
    float4 o1 = make_float4(e[4]*inv, e[5]*inv, e[6]*inv, e[7]*inv);
    float4* dst = reinterpret_cast<float4*>(g_attn + ((size_t)h*L_ + q)*M_);
    dst[0] = o0;
    dst[1] = o1;
}

// ---------------------------------------------------------------------------
// Kernel D: context via smem tiles + TMA bulk stores (bypass L1/STG path).
// grid 512: each block owns a 1024q x 64d = 256KB contiguous slab,
// written as 16 double-buffered 16KB cp.async.bulk stores.
// ---------------------------------------------------------------------------
__global__ __launch_bounds__(256, 2)
void ctx_kernel(float* __restrict__ out)
{
    __shared__ float4 sV4[M_*16];          // 2KB  Vs[b,h]
    __shared__ float4 sA4[64*2];           // 2KB  attn subtile (64 q x 8 k)
    __shared__ float  sOut[2][4096];       // 32KB double-buffered output tiles

    const int tid = threadIdx.x;
    const int qq  = blockIdx.x & 3;
    const int h   = (blockIdx.x >> 2) & 15;
    const int b   = blockIdx.x >> 6;

    if (tid < 128)
        sV4[tid] = reinterpret_cast<const float4*>(g_Vs)[(size_t)(b*H_ + h)*128 + tid];

    const int dq = tid & 15;
    const int q0 = tid >> 4;
    const size_t outBase = (((size_t)b*H_ + h) * L_ + (size_t)qq*1024) * D_;
    const float4* gA4 = reinterpret_cast<const float4*>(g_attn) +
                        ((size_t)h * L_ + (size_t)qq*1024) * 2;

    for (int s = 0; s < 16; ++s) {
        const int p = s & 1;
        if (tid == 0 && s >= 2)
            asm volatile("cp.async.bulk.wait_group 1;" ::: "memory");
        __syncthreads();
        if (tid < 128)
            sA4[tid] = gA4[(size_t)s*128 + tid];
        __syncthreads();

        float4* o4 = reinterpret_cast<float4*>(sOut[p]);
#pragma unroll
        for (int i = 0; i < 4; ++i) {
            int ql = i*16 + q0;
            float4 a0 = sA4[ql*2], a1 = sA4[ql*2 + 1];
            float aw[8] = {a0.x, a0.y, a0.z, a0.w, a1.x, a1.y, a1.z, a1.w};
            float4 acc = make_float4(0.f, 0.f, 0.f, 0.f);
#pragma unroll
            for (int k = 0; k < 8; ++k) {
                float4 v = sV4[k*16 + dq];
                acc.x = fmaf(aw[k], v.x, acc.x);
                acc.y = fmaf(aw[k], v.y, acc.y);
                acc.z = fmaf(aw[k], v.z, acc.z);
                acc.w = fmaf(aw[k], v.w, acc.w);
            }
            o4[ql*16 + dq] = acc;
        }
        __syncthreads();
        if (tid == 0) {
            asm volatile("fence.proxy.async.shared::cta;" ::: "memory");
            unsigned int saddr = (unsigned int)__cvta_generic_to_shared(&sOut[p][0]);
            const float* gdst = out + outBase + (size_t)s * 4096;
            asm volatile("cp.async.bulk.global.shared::cta.bulk_group [%0], [%1], %2;"
                         :: "l"(gdst), "r"(saddr), "r"(16384) : "memory");
            asm volatile("cp.async.bulk.commit_group;" ::: "memory");
        }
    }
    if (tid == 0)
        asm volatile("cp.async.bulk.wait_group 0;" ::: "memory");
}

// ---------------------------------------------------------------------------
extern "C" void kernel_launch(void* const* d_in, const int* in_sizes, int n_in,
                              void* d_out, int out_size)
{
    const float* Q   = (const float*)d_in[0];
    const float* K   = (const float*)d_in[1];
    const float* V   = (const float*)d_in[2];
    const float* Wsk = (const float*)d_in[3];
    const float* bsk = (const float*)d_in[4];
    const float* Wsv = (const float*)d_in[5];
    const float* bsv = (const float*)d_in[6];
    const float* Wpc = (const float*)d_in[7];
    const float* bpc = (const float*)d_in[8];
    const float* Wq  = (const float*)d_in[9];
    const float* bq  = (const float*)d_in[10];
    const float* Wk  = (const float*)d_in[11];
    const float* bk  = (const float*)d_in[12];
    float* out = (float*)d_out;

    shrink_kernel<<<dim3(128, 4), 256>>>(K, V, Wsk, Wsv);
    reduce_kernel<<<64, 256>>>(bsk, bsv);
    cluster_kernel<<<1, 256>>>(Wpc, bpc, Wq, bq, Wk, bk, out, (long long)out_size);
    attn_kernel<<<H_*32, 128>>>(Q);
    ctx_kernel<<<512, 256>>>(out);
}